// round 3
// baseline (speedup 1.0000x reference)
#include <cuda_runtime.h>
#include <math.h>
#include <stdint.h>

#define Nn 2048
#define Dd 4096
#define NC 21
#define NBB 84
#define NOUT 105

// JAX >= 0.4.36 defaults jax_threefry_partitionable=True (fold-like split,
// xor-of-halves 32-bit random bits). Set to 0 to emulate the legacy path.
#define JAX_PARTITIONABLE 1

// ---------------- scratch (static device globals; no allocations) ----------
__device__ float g_Z[(size_t)Nn * Dd];
__device__ float g_X[(size_t)Nn * Dd];
__device__ float g_bx1[Nn], g_by1[Nn], g_bx2[Nn], g_by2[Nn];
__device__ float g_area[Nn], g_cx[Nn], g_cy[Nn];
__device__ float g_len[Nn];
__device__ int   g_cols[Nn * 5];
__device__ float g_vals[Nn * 5];
__device__ int   g_cnt[Nn];
__device__ unsigned g_keys[6];

// ---------------- threefry-2x32 (bit-exact vs jax) --------------------------
__device__ __forceinline__ unsigned rotl32_(unsigned x, int r) {
    return (x << r) | (x >> (32 - r));
}

__device__ __forceinline__ void tf2x32(unsigned k0, unsigned k1,
                                       unsigned x0, unsigned x1,
                                       unsigned& o0, unsigned& o1) {
    unsigned ks2 = k0 ^ k1 ^ 0x1BD11BDAu;
    x0 += k0; x1 += k1;
#define TFR(r) { x0 += x1; x1 = rotl32_(x1, r); x1 ^= x0; }
    TFR(13) TFR(15) TFR(26) TFR(6)
    x0 += k1; x1 += ks2 + 1u;
    TFR(17) TFR(29) TFR(16) TFR(24)
    x0 += ks2; x1 += k0 + 2u;
    TFR(13) TFR(15) TFR(26) TFR(6)
    x0 += k0; x1 += k1 + 3u;
    TFR(17) TFR(29) TFR(16) TFR(24)
    x0 += k1; x1 += ks2 + 4u;
    TFR(13) TFR(15) TFR(26) TFR(6)
    x0 += ks2; x1 += k0 + 5u;
#undef TFR
    o0 = x0; o1 = x1;
}

// uniform [0,1) for flat element m of an (Nn,Nn) array under key (k0,k1)
__device__ __forceinline__ float jax_uniform(unsigned k0, unsigned k1, unsigned m) {
    unsigned o0, o1, bits;
#if JAX_PARTITIONABLE
    // 64-bit counter = flat index (hi=0, lo=m); 32-bit bits = y0 ^ y1
    tf2x32(k0, k1, 0u, m, o0, o1);
    bits = o0 ^ o1;
#else
    const unsigned half = (unsigned)(Nn) * (unsigned)(Nn) / 2u;
    if (m < half) { tf2x32(k0, k1, m, m + half, o0, o1); bits = o0; }
    else          { tf2x32(k0, k1, m - half, m, o0, o1); bits = o1; }
#endif
    return __uint_as_float((bits >> 9) | 0x3F800000u) - 1.0f;
}

__global__ void k_keys() {
    unsigned o0, o1;
#if JAX_PARTITIONABLE
    // fold-like split: key_i = threefry(rootkey, (0, i))
    for (unsigned i = 0; i < 3; i++) {
        tf2x32(0u, 42u, 0u, i, o0, o1);
        g_keys[2 * i] = o0; g_keys[2 * i + 1] = o1;
    }
#else
    // original split: counts iota(6) -> halves (0,1,2)/(3,4,5), concat, reshape(3,2)
    tf2x32(0u, 42u, 0u, 3u, o0, o1); g_keys[0] = o0; g_keys[3] = o1;
    tf2x32(0u, 42u, 1u, 4u, o0, o1); g_keys[1] = o0; g_keys[4] = o1;
    tf2x32(0u, 42u, 2u, 5u, o0, o1); g_keys[2] = o0; g_keys[5] = o1;
#endif
}

// ---------------- box prep + row norms --------------------------------------
__global__ void k_boxprep(const float* __restrict__ rois) {
    int i = blockIdx.x * blockDim.x + threadIdx.x;
    if (i < Nn) {
        float x1 = rois[i * 5 + 1], y1 = rois[i * 5 + 2];
        float x2 = rois[i * 5 + 3], y2 = rois[i * 5 + 4];
        g_bx1[i] = x1; g_by1[i] = y1; g_bx2[i] = x2; g_by2[i] = y2;
        g_area[i] = (x2 - x1 + 1.0f) * (y2 - y1 + 1.0f);
        g_cx[i] = (x1 + x2) * 0.5f;
        g_cy[i] = (y1 + y2) * 0.5f;
    }
}

__global__ void k_lens(const float* __restrict__ P) {
    int i = blockIdx.x;
    const float4* P4 = (const float4*)(P + (size_t)i * Dd);
    float acc = 0.f;
    for (int q = threadIdx.x; q < Dd / 4; q += blockDim.x) {
        float4 v = P4[q];
        acc += v.x * v.x + v.y * v.y + v.z * v.z + v.w * v.w;
    }
    __shared__ float red[8];
    for (int o = 16; o; o >>= 1) acc += __shfl_xor_sync(0xffffffffu, acc, o);
    if ((threadIdx.x & 31) == 0) red[threadIdx.x >> 5] = acc;
    __syncthreads();
    if (threadIdx.x == 0) {
        float s = 0.f;
        for (int w = 0; w < 8; w++) s += red[w];
        g_len[i] = sqrtf(s);
    }
}

// ---------------- mask construction (one block per row) ---------------------
__global__ void k_mask() {
    int i = blockIdx.x;
    __shared__ float p1[Nn]; __shared__ int id1[Nn];
    __shared__ float p2[Nn]; __shared__ int id2[Nn];
    __shared__ int n1, n2;
    if (threadIdx.x == 0) { n1 = 0; n2 = 0; }
    __syncthreads();

    float xi1 = g_bx1[i], yi1 = g_by1[i], xi2 = g_bx2[i], yi2 = g_by2[i];
    float ai = g_area[i], cxi = g_cx[i], cyi = g_cy[i];
    unsigned K1a = g_keys[0], K1b = g_keys[1];
    unsigned K2a = g_keys[2], K2b = g_keys[3];

    for (int j = threadIdx.x; j < Nn; j += blockDim.x) {
        float iw = fminf(xi2, g_bx2[j]) - fmaxf(xi1, g_bx1[j]) + 1.0f;
        float ih = fminf(yi2, g_by2[j]) - fmaxf(yi1, g_by1[j]) + 1.0f;
        iw = fmaxf(iw, 0.0f); ih = fmaxf(ih, 0.0f);
        float inter = iw * ih;
        float iou = inter / (ai + g_area[j] - inter);
        if (iou >= 0.7f) {
            int p = atomicAdd(&n1, 1);
            p1[p] = jax_uniform(K1a, K1b, (unsigned)(i * Nn + j));
            id1[p] = j;
        }
        float dx = cxi - g_cx[j], dy = cyi - g_cy[j];
        float dist = sqrtf(dx * dx + dy * dy) / 1000.0f;
        if (dist < 0.01f) {
            int p = atomicAdd(&n2, 1);
            p2[p] = jax_uniform(K2a, K2b, (unsigned)(i * Nn + j));
            id2[p] = j;
        }
    }
    __syncthreads();

    if (threadIdx.x == 0) {
        int U[12]; float pu[12]; int nu = 0;
        // top-6 of iou-candidates by pri (value desc, index asc == lax.top_k)
        int m1 = n1 < 6 ? n1 : 6;
        for (int k = 0; k < m1; k++) {
            int best = -1, bi = 0x7fffffff; float bp = -1.0f;
            for (int t = 0; t < n1; t++) {
                float v = p1[t];
                if (v < -1.0f) continue;  // already taken
                if (v > bp || (v == bp && id1[t] < bi)) { best = t; bp = v; bi = id1[t]; }
            }
            p1[best] = -2.0f;
            U[nu++] = bi;  // distinct within list1
        }
        // top-6 of dist-candidates, deduped into union
        int m2 = n2 < 6 ? n2 : 6;
        for (int k = 0; k < m2; k++) {
            int best = -1, bi = 0x7fffffff; float bp = -1.0f;
            for (int t = 0; t < n2; t++) {
                float v = p2[t];
                if (v < -1.0f) continue;
                if (v > bp || (v == bp && id2[t] < bi)) { best = t; bp = v; bi = id2[t]; }
            }
            p2[best] = -2.0f;
            bool dup = false;
            for (int t = 0; t < nu; t++) if (U[t] == bi) { dup = true; break; }
            if (!dup) U[nu++] = bi;
        }
        // top-4 of union by third uniform
        unsigned K3a = g_keys[4], K3b = g_keys[5];
        for (int t = 0; t < nu; t++)
            pu[t] = jax_uniform(K3a, K3b, (unsigned)(i * Nn + U[t]));
        int F[4]; int nf = nu < 4 ? nu : 4;
        for (int k = 0; k < nf; k++) {
            int best = -1, bi = 0x7fffffff; float bp = -1.0f;
            for (int t = 0; t < nu; t++) {
                float v = pu[t];
                if (v < -1.0f) continue;
                if (v > bp || (v == bp && U[t] < bi)) { best = t; bp = v; bi = U[t]; }
            }
            pu[best] = -2.0f;
            F[k] = bi;
        }
        // final row support: diag + selected (dedup self)
        int cols[5]; int cnt = 0;
        cols[cnt++] = i;
        for (int k = 0; k < nf; k++) if (F[k] != i) cols[cnt++] = F[k];
        g_cnt[i] = cnt;
        for (int e = 0; e < cnt; e++) g_cols[i * 5 + e] = cols[e];
    }
}

// ---------------- sim values at the <=5 selected positions ------------------
__global__ void k_sim(const float* __restrict__ P) {
    int i = blockIdx.x;
    __shared__ float xs[Dd];
    int tid = threadIdx.x;
    const float4* Pi = (const float4*)(P + (size_t)i * Dd);
    float4* xs4 = (float4*)xs;
    for (int q = tid; q < Dd / 4; q += blockDim.x) xs4[q] = Pi[q];
    __syncthreads();
    int w = tid >> 5, lane = tid & 31;
    int cnt = g_cnt[i];
    if (w < cnt) {
        int j = g_cols[i * 5 + w];
        const float4* Pj = (const float4*)(P + (size_t)j * Dd);
        float acc = 0.f;
        for (int q = lane; q < Dd / 4; q += 32) {
            float4 a = xs4[q], b = Pj[q];
            acc += a.x * b.x + a.y * b.y + a.z * b.z + a.w * b.w;
        }
        for (int o = 16; o; o >>= 1) acc += __shfl_xor_sync(0xffffffffu, acc, o);
        if (lane == 0) g_vals[i * 5 + w] = acc / (g_len[i] * g_len[j]);
    }
}

// ---------------- sparse adj apply: g_Z[i] = sum_e val_e * src[col_e] -------
__global__ void k_sparse(const float* __restrict__ src) {
    int i = blockIdx.x;
    int cnt = g_cnt[i];
    int   cols[5]; float vals[5];
    for (int e = 0; e < cnt; e++) { cols[e] = g_cols[i * 5 + e]; vals[e] = g_vals[i * 5 + e]; }
    const float4* S4 = (const float4*)src;
    float4* Z4 = (float4*)(g_Z + (size_t)i * Dd);
    for (int q = threadIdx.x; q < Dd / 4; q += blockDim.x) {
        float4 acc = make_float4(0.f, 0.f, 0.f, 0.f);
        for (int e = 0; e < cnt; e++) {
            float4 p = S4[(size_t)cols[e] * (Dd / 4) + q];
            float v = vals[e];
            acc.x += v * p.x; acc.y += v * p.y; acc.z += v * p.z; acc.w += v * p.w;
        }
        Z4[q] = acc;
    }
}

// ---------------- SGEMM: g_X = relu(g_Z @ B + bias), 2048x4096x4096 ---------
__global__ __launch_bounds__(256, 2)
void k_gemm(const float* __restrict__ B, const float* __restrict__ bias) {
    const int M = Nn, N = Dd, K = Dd;
    __shared__ float As[16][128];
    __shared__ float Bs[16][128];
    int tid = threadIdx.x;
    int bx = blockIdx.x, by = blockIdx.y;

    int arow = tid >> 2;            // 0..63
    int acol = (tid & 3) << 2;      // 0,4,8,12
    const float* Ap = g_Z + (size_t)(by * 128 + arow) * K + acol;

    int brow = tid >> 5;            // 0..7
    int bcol = (tid & 31) << 2;     // 0..124
    const float* Bp = B + (size_t)brow * N + bx * 128 + bcol;

    int tm = (tid >> 4) << 3;
    int tn = (tid & 15) << 3;

    float acc[8][8];
#pragma unroll
    for (int u = 0; u < 8; u++)
#pragma unroll
        for (int v = 0; v < 8; v++) acc[u][v] = 0.f;

    float4 pa0 = *(const float4*)Ap;
    float4 pa1 = *(const float4*)(Ap + (size_t)64 * K);
    float4 pb0 = *(const float4*)Bp;
    float4 pb1 = *(const float4*)(Bp + (size_t)8 * N);

    const int nk = K >> 4;
    for (int kt = 0; kt < nk; kt++) {
        As[acol + 0][arow] = pa0.x; As[acol + 1][arow] = pa0.y;
        As[acol + 2][arow] = pa0.z; As[acol + 3][arow] = pa0.w;
        As[acol + 0][arow + 64] = pa1.x; As[acol + 1][arow + 64] = pa1.y;
        As[acol + 2][arow + 64] = pa1.z; As[acol + 3][arow + 64] = pa1.w;
        *(float4*)&Bs[brow][bcol] = pb0;
        *(float4*)&Bs[brow + 8][bcol] = pb1;
        __syncthreads();
        if (kt + 1 < nk) {
            Ap += 16; Bp += (size_t)16 * N;
            pa0 = *(const float4*)Ap;
            pa1 = *(const float4*)(Ap + (size_t)64 * K);
            pb0 = *(const float4*)Bp;
            pb1 = *(const float4*)(Bp + (size_t)8 * N);
        }
#pragma unroll
        for (int k = 0; k < 16; k++) {
            float a[8], b[8];
            *(float4*)&a[0] = *(const float4*)&As[k][tm];
            *(float4*)&a[4] = *(const float4*)&As[k][tm + 4];
            *(float4*)&b[0] = *(const float4*)&Bs[k][tn];
            *(float4*)&b[4] = *(const float4*)&Bs[k][tn + 4];
#pragma unroll
            for (int u = 0; u < 8; u++)
#pragma unroll
                for (int v = 0; v < 8; v++)
                    acc[u][v] += a[u] * b[v];
        }
        __syncthreads();
    }

    int crow = by * 128 + tm;
    int ccol = bx * 128 + tn;
    float bb[8];
    *(float4*)&bb[0] = *(const float4*)(bias + ccol);
    *(float4*)&bb[4] = *(const float4*)(bias + ccol + 4);
#pragma unroll
    for (int u = 0; u < 8; u++) {
        float4 o0, o1;
        o0.x = fmaxf(acc[u][0] + bb[0], 0.f);
        o0.y = fmaxf(acc[u][1] + bb[1], 0.f);
        o0.z = fmaxf(acc[u][2] + bb[2], 0.f);
        o0.w = fmaxf(acc[u][3] + bb[3], 0.f);
        o1.x = fmaxf(acc[u][4] + bb[4], 0.f);
        o1.y = fmaxf(acc[u][5] + bb[5], 0.f);
        o1.z = fmaxf(acc[u][6] + bb[6], 0.f);
        o1.w = fmaxf(acc[u][7] + bb[7], 0.f);
        *(float4*)(g_X + (size_t)(crow + u) * N + ccol) = o0;
        *(float4*)(g_X + (size_t)(crow + u) * N + ccol + 4) = o1;
    }
}

// ---------------- heads: softmax(X@Wc+bc) ++ X@Wb+bb (2 rows / block) -------
__global__ void k_heads(const float* __restrict__ Wc, const float* __restrict__ bc,
                        const float* __restrict__ Wb, const float* __restrict__ bb_,
                        float* __restrict__ out) {
    int r0 = blockIdx.x * 2;
    __shared__ float xs0[Dd], xs1[Dd];
    int tid = threadIdx.x;  // 128
    const float4* X4 = (const float4*)g_X;
    float4* a4 = (float4*)xs0; float4* b4 = (float4*)xs1;
    for (int q = tid; q < Dd / 4; q += 128) {
        a4[q] = X4[(size_t)r0 * (Dd / 4) + q];
        b4[q] = X4[(size_t)(r0 + 1) * (Dd / 4) + q];
    }
    __syncthreads();

    float a0 = 0.f, a1 = 0.f;
    int n = tid;
    if (n < NOUT) {
        const float* wp; int stride; int c;
        if (n < NC) { c = n;      wp = Wc + c; stride = NC; }
        else        { c = n - NC; wp = Wb + c; stride = NBB; }
#pragma unroll 8
        for (int k = 0; k < Dd; k++) {
            float w = wp[(size_t)k * stride];
            a0 += xs0[k] * w;
            a1 += xs1[k] * w;
        }
        if (n < NC) { a0 += bc[c]; a1 += bc[c]; }
        else        { a0 += bb_[c]; a1 += bb_[c]; }
    }
    if (tid < 32) {
        float v0 = (tid < NC) ? a0 : -3.4e38f;
        float v1 = (tid < NC) ? a1 : -3.4e38f;
        float m0 = v0, m1 = v1;
        for (int o = 16; o; o >>= 1) {
            m0 = fmaxf(m0, __shfl_xor_sync(0xffffffffu, m0, o));
            m1 = fmaxf(m1, __shfl_xor_sync(0xffffffffu, m1, o));
        }
        float e0 = (tid < NC) ? expf(a0 - m0) : 0.f;
        float e1 = (tid < NC) ? expf(a1 - m1) : 0.f;
        float s0 = e0, s1 = e1;
        for (int o = 16; o; o >>= 1) {
            s0 += __shfl_xor_sync(0xffffffffu, s0, o);
            s1 += __shfl_xor_sync(0xffffffffu, s1, o);
        }
        if (tid < NC) {
            out[(size_t)r0 * NOUT + tid] = e0 / s0;
            out[(size_t)(r0 + 1) * NOUT + tid] = e1 / s1;
        }
    }
    if (n >= NC && n < NOUT) {
        out[(size_t)r0 * NOUT + n] = a0;
        out[(size_t)(r0 + 1) * NOUT + n] = a1;
    }
}

// ---------------- host orchestration ----------------------------------------
extern "C" void kernel_launch(void* const* d_in, const int* in_sizes, int n_in,
                              void* d_out, int out_size) {
    const float* rois = (const float*)d_in[0];
    const float* P    = (const float*)d_in[1];
    const float* W1   = (const float*)d_in[2];
    const float* b1   = (const float*)d_in[3];
    const float* W2   = (const float*)d_in[4];
    const float* b2   = (const float*)d_in[5];
    const float* Wc   = (const float*)d_in[6];
    const float* bc   = (const float*)d_in[7];
    const float* Wb   = (const float*)d_in[8];
    const float* bb   = (const float*)d_in[9];
    float* out = (float*)d_out;

    void* xaddr = nullptr;
    cudaGetSymbolAddress(&xaddr, g_X);

    k_keys<<<1, 1>>>();
    k_boxprep<<<(Nn + 255) / 256, 256>>>(rois);
    k_lens<<<Nn, 256>>>(P);
    k_mask<<<Nn, 256>>>();
    k_sim<<<Nn, 256>>>(P);

    k_sparse<<<Nn, 256>>>(P);                       // g_Z = adj @ P
    k_gemm<<<dim3(Dd / 128, Nn / 128), 256>>>(W1, b1);  // g_X = relu(g_Z@W1+b1)
    k_sparse<<<Nn, 256>>>((const float*)xaddr);     // g_Z = adj @ g_X
    k_gemm<<<dim3(Dd / 128, Nn / 128), 256>>>(W2, b2);  // g_X = relu(g_Z@W2+b2)

    k_heads<<<Nn / 2, 128>>>(Wc, bc, Wb, bb, out);
}

// round 6
// speedup vs baseline: 1.9797x; 1.9797x over previous
#include <cuda_runtime.h>
#include <cuda_bf16.h>
#include <math.h>
#include <stdint.h>

#define Nn 2048
#define Dd 4096
#define NC 21
#define NBB 84
#define NOUT 105

#define JAX_PARTITIONABLE 1

// ---------------- scratch (static device globals; no allocations) ----------
__device__ float g_Z[(size_t)Nn * Dd];
__device__ float g_X[(size_t)Nn * Dd];
__device__ __nv_bfloat16 gAh[(size_t)Nn * Dd];
__device__ __nv_bfloat16 gAl[(size_t)Nn * Dd];
__device__ __nv_bfloat16 gBh[(size_t)Dd * Dd];   // transposed: [N][K]
__device__ __nv_bfloat16 gBl[(size_t)Dd * Dd];
__device__ float g_bx1[Nn], g_by1[Nn], g_bx2[Nn], g_by2[Nn];
__device__ float g_area[Nn], g_cx[Nn], g_cy[Nn];
__device__ float g_len[Nn];
__device__ int   g_cols[Nn * 5];
__device__ float g_vals[Nn * 5];
__device__ int   g_cnt[Nn];
__device__ unsigned g_keys[6];

// ---------------- threefry-2x32 (bit-exact vs jax) --------------------------
__device__ __forceinline__ unsigned rotl32_(unsigned x, int r) {
    return (x << r) | (x >> (32 - r));
}

__device__ __forceinline__ void tf2x32(unsigned k0, unsigned k1,
                                       unsigned x0, unsigned x1,
                                       unsigned& o0, unsigned& o1) {
    unsigned ks2 = k0 ^ k1 ^ 0x1BD11BDAu;
    x0 += k0; x1 += k1;
#define TFR(r) { x0 += x1; x1 = rotl32_(x1, r); x1 ^= x0; }
    TFR(13) TFR(15) TFR(26) TFR(6)
    x0 += k1; x1 += ks2 + 1u;
    TFR(17) TFR(29) TFR(16) TFR(24)
    x0 += ks2; x1 += k0 + 2u;
    TFR(13) TFR(15) TFR(26) TFR(6)
    x0 += k0; x1 += k1 + 3u;
    TFR(17) TFR(29) TFR(16) TFR(24)
    x0 += k1; x1 += ks2 + 4u;
    TFR(13) TFR(15) TFR(26) TFR(6)
    x0 += ks2; x1 += k0 + 5u;
#undef TFR
    o0 = x0; o1 = x1;
}

__device__ __forceinline__ float jax_uniform(unsigned k0, unsigned k1, unsigned m) {
    unsigned o0, o1, bits;
#if JAX_PARTITIONABLE
    tf2x32(k0, k1, 0u, m, o0, o1);
    bits = o0 ^ o1;
#else
    const unsigned half = (unsigned)(Nn) * (unsigned)(Nn) / 2u;
    if (m < half) { tf2x32(k0, k1, m, m + half, o0, o1); bits = o0; }
    else          { tf2x32(k0, k1, m - half, m, o0, o1); bits = o1; }
#endif
    return __uint_as_float((bits >> 9) | 0x3F800000u) - 1.0f;
}

__global__ void k_keys() {
    unsigned o0, o1;
#if JAX_PARTITIONABLE
    for (unsigned i = 0; i < 3; i++) {
        tf2x32(0u, 42u, 0u, i, o0, o1);
        g_keys[2 * i] = o0; g_keys[2 * i + 1] = o1;
    }
#else
    tf2x32(0u, 42u, 0u, 3u, o0, o1); g_keys[0] = o0; g_keys[3] = o1;
    tf2x32(0u, 42u, 1u, 4u, o0, o1); g_keys[1] = o0; g_keys[4] = o1;
    tf2x32(0u, 42u, 2u, 5u, o0, o1); g_keys[2] = o0; g_keys[5] = o1;
#endif
}

// ---------------- box prep + row norms --------------------------------------
__global__ void k_boxprep(const float* __restrict__ rois) {
    int i = blockIdx.x * blockDim.x + threadIdx.x;
    if (i < Nn) {
        float x1 = rois[i * 5 + 1], y1 = rois[i * 5 + 2];
        float x2 = rois[i * 5 + 3], y2 = rois[i * 5 + 4];
        g_bx1[i] = x1; g_by1[i] = y1; g_bx2[i] = x2; g_by2[i] = y2;
        g_area[i] = (x2 - x1 + 1.0f) * (y2 - y1 + 1.0f);
        g_cx[i] = (x1 + x2) * 0.5f;
        g_cy[i] = (y1 + y2) * 0.5f;
    }
}

__global__ void k_lens(const float* __restrict__ P) {
    int i = blockIdx.x;
    const float4* P4 = (const float4*)(P + (size_t)i * Dd);
    float acc = 0.f;
    for (int q = threadIdx.x; q < Dd / 4; q += blockDim.x) {
        float4 v = P4[q];
        acc += v.x * v.x + v.y * v.y + v.z * v.z + v.w * v.w;
    }
    __shared__ float red[8];
    for (int o = 16; o; o >>= 1) acc += __shfl_xor_sync(0xffffffffu, acc, o);
    if ((threadIdx.x & 31) == 0) red[threadIdx.x >> 5] = acc;
    __syncthreads();
    if (threadIdx.x == 0) {
        float s = 0.f;
        for (int w = 0; w < 8; w++) s += red[w];
        g_len[i] = sqrtf(s);
    }
}

// ---------------- mask construction (one block per row) ---------------------
__global__ void k_mask() {
    int i = blockIdx.x;
    __shared__ float p1[Nn]; __shared__ int id1[Nn];
    __shared__ float p2[Nn]; __shared__ int id2[Nn];
    __shared__ int n1, n2;
    if (threadIdx.x == 0) { n1 = 0; n2 = 0; }
    __syncthreads();

    float xi1 = g_bx1[i], yi1 = g_by1[i], xi2 = g_bx2[i], yi2 = g_by2[i];
    float ai = g_area[i], cxi = g_cx[i], cyi = g_cy[i];
    unsigned K1a = g_keys[0], K1b = g_keys[1];
    unsigned K2a = g_keys[2], K2b = g_keys[3];

    for (int j = threadIdx.x; j < Nn; j += blockDim.x) {
        float iw = fminf(xi2, g_bx2[j]) - fmaxf(xi1, g_bx1[j]) + 1.0f;
        float ih = fminf(yi2, g_by2[j]) - fmaxf(yi1, g_by1[j]) + 1.0f;
        iw = fmaxf(iw, 0.0f); ih = fmaxf(ih, 0.0f);
        float inter = iw * ih;
        float iou = inter / (ai + g_area[j] - inter);
        if (iou >= 0.7f) {
            int p = atomicAdd(&n1, 1);
            p1[p] = jax_uniform(K1a, K1b, (unsigned)(i * Nn + j));
            id1[p] = j;
        }
        float dx = cxi - g_cx[j], dy = cyi - g_cy[j];
        float dist = sqrtf(dx * dx + dy * dy) / 1000.0f;
        if (dist < 0.01f) {
            int p = atomicAdd(&n2, 1);
            p2[p] = jax_uniform(K2a, K2b, (unsigned)(i * Nn + j));
            id2[p] = j;
        }
    }
    __syncthreads();

    if (threadIdx.x == 0) {
        int U[12]; float pu[12]; int nu = 0;
        int m1 = n1 < 6 ? n1 : 6;
        for (int k = 0; k < m1; k++) {
            int best = -1, bi = 0x7fffffff; float bp = -1.0f;
            for (int t = 0; t < n1; t++) {
                float v = p1[t];
                if (v < -1.0f) continue;
                if (v > bp || (v == bp && id1[t] < bi)) { best = t; bp = v; bi = id1[t]; }
            }
            p1[best] = -2.0f;
            U[nu++] = bi;
        }
        int m2 = n2 < 6 ? n2 : 6;
        for (int k = 0; k < m2; k++) {
            int best = -1, bi = 0x7fffffff; float bp = -1.0f;
            for (int t = 0; t < n2; t++) {
                float v = p2[t];
                if (v < -1.0f) continue;
                if (v > bp || (v == bp && id2[t] < bi)) { best = t; bp = v; bi = id2[t]; }
            }
            p2[best] = -2.0f;
            bool dup = false;
            for (int t = 0; t < nu; t++) if (U[t] == bi) { dup = true; break; }
            if (!dup) U[nu++] = bi;
        }
        unsigned K3a = g_keys[4], K3b = g_keys[5];
        for (int t = 0; t < nu; t++)
            pu[t] = jax_uniform(K3a, K3b, (unsigned)(i * Nn + U[t]));
        int F[4]; int nf = nu < 4 ? nu : 4;
        for (int k = 0; k < nf; k++) {
            int best = -1, bi = 0x7fffffff; float bp = -1.0f;
            for (int t = 0; t < nu; t++) {
                float v = pu[t];
                if (v < -1.0f) continue;
                if (v > bp || (v == bp && U[t] < bi)) { best = t; bp = v; bi = U[t]; }
            }
            pu[best] = -2.0f;
            F[k] = bi;
        }
        int cols[5]; int cnt = 0;
        cols[cnt++] = i;
        for (int k = 0; k < nf; k++) if (F[k] != i) cols[cnt++] = F[k];
        g_cnt[i] = cnt;
        for (int e = 0; e < cnt; e++) g_cols[i * 5 + e] = cols[e];
    }
}

// ---------------- sim values at the <=5 selected positions ------------------
__global__ void k_sim(const float* __restrict__ P) {
    int i = blockIdx.x;
    __shared__ float xs[Dd];
    int tid = threadIdx.x;
    const float4* Pi = (const float4*)(P + (size_t)i * Dd);
    float4* xs4 = (float4*)xs;
    for (int q = tid; q < Dd / 4; q += blockDim.x) xs4[q] = Pi[q];
    __syncthreads();
    int w = tid >> 5, lane = tid & 31;
    int cnt = g_cnt[i];
    if (w < cnt) {
        int j = g_cols[i * 5 + w];
        const float4* Pj = (const float4*)(P + (size_t)j * Dd);
        float acc = 0.f;
        for (int q = lane; q < Dd / 4; q += 32) {
            float4 a = xs4[q], b = Pj[q];
            acc += a.x * b.x + a.y * b.y + a.z * b.z + a.w * b.w;
        }
        for (int o = 16; o; o >>= 1) acc += __shfl_xor_sync(0xffffffffu, acc, o);
        if (lane == 0) g_vals[i * 5 + w] = acc / (g_len[i] * g_len[j]);
    }
}

// ---------------- sparse adj apply: g_Z[i] = sum_e val_e * src[col_e] -------
__global__ void k_sparse(const float* __restrict__ src) {
    int i = blockIdx.x;
    int cnt = g_cnt[i];
    int   cols[5]; float vals[5];
    for (int e = 0; e < cnt; e++) { cols[e] = g_cols[i * 5 + e]; vals[e] = g_vals[i * 5 + e]; }
    const float4* S4 = (const float4*)src;
    float4* Z4 = (float4*)(g_Z + (size_t)i * Dd);
    for (int q = threadIdx.x; q < Dd / 4; q += blockDim.x) {
        float4 acc = make_float4(0.f, 0.f, 0.f, 0.f);
        for (int e = 0; e < cnt; e++) {
            float4 p = S4[(size_t)cols[e] * (Dd / 4) + q];
            float v = vals[e];
            acc.x += v * p.x; acc.y += v * p.y; acc.z += v * p.z; acc.w += v * p.w;
        }
        Z4[q] = acc;
    }
}

// ---------------- fp32 -> bf16 hi/lo split of A (g_Z) -----------------------
__global__ void k_cvtA() {
    size_t i = ((size_t)blockIdx.x * 256 + threadIdx.x) * 4;
    float4 v = *(const float4*)(g_Z + i);
    float vv[4] = {v.x, v.y, v.z, v.w};
#pragma unroll
    for (int q = 0; q < 4; q++) {
        __nv_bfloat16 h = __float2bfloat16(vv[q]);
        __nv_bfloat16 l = __float2bfloat16(vv[q] - __bfloat162float(h));
        gAh[i + q] = h;
        gAl[i + q] = l;
    }
}

// ---------------- W[K][N] fp32 -> WT hi/lo bf16 [N][K] (transpose+split) ----
__global__ void k_cvtW(const float* __restrict__ W) {
    __shared__ float ts[32][33];
    int n0 = blockIdx.x * 32, k0 = blockIdx.y * 32;
    int tx = threadIdx.x & 31, ty = threadIdx.x >> 5;  // 32 x 8
#pragma unroll
    for (int q = 0; q < 4; q++) {
        int r = ty + q * 8;  // k within tile
        ts[r][tx] = W[(size_t)(k0 + r) * Dd + n0 + tx];
    }
    __syncthreads();
#pragma unroll
    for (int q = 0; q < 4; q++) {
        int n = ty + q * 8;  // n within tile
        float x = ts[tx][n];
        __nv_bfloat16 h = __float2bfloat16(x);
        __nv_bfloat16 l = __float2bfloat16(x - __bfloat162float(h));
        size_t o = (size_t)(n0 + n) * Dd + k0 + tx;
        gBh[o] = h;
        gBl[o] = l;
    }
}

// ---------------- mma.sync helpers ------------------------------------------
__device__ __forceinline__ uint32_t smem_u32(const void* p) {
    uint32_t a;
    asm("{ .reg .u64 t; cvta.to.shared.u64 t, %1; cvt.u32.u64 %0, t; }"
        : "=r"(a) : "l"(p));
    return a;
}

__device__ __forceinline__ void ldsm4(uint32_t* r, uint32_t addr) {
    asm volatile("ldmatrix.sync.aligned.m8n8.x4.shared.b16 {%0,%1,%2,%3}, [%4];"
                 : "=r"(r[0]), "=r"(r[1]), "=r"(r[2]), "=r"(r[3]) : "r"(addr));
}

__device__ __forceinline__ void mma16816(float* d, const uint32_t* a,
                                         const uint32_t* b) {
    asm volatile(
        "mma.sync.aligned.m16n8k16.row.col.f32.bf16.bf16.f32 "
        "{%0,%1,%2,%3}, {%4,%5,%6,%7}, {%8,%9}, {%0,%1,%2,%3};"
        : "+f"(d[0]), "+f"(d[1]), "+f"(d[2]), "+f"(d[3])
        : "r"(a[0]), "r"(a[1]), "r"(a[2]), "r"(a[3]), "r"(b[0]), "r"(b[1]));
}

// ---------------- split-bf16 tensor GEMM: g_X = relu(A@W + bias) ------------
// CTA tile 128(M) x 128(N), K-chunk 32. 8 warps as 2(M) x 4(N), warp 64x32.
// smem per term tile: 128 rows x 40 bf16 (padded) = 10240 B; 4 tiles = 40960 B.
#define KC 32
#define STR 40
#define TILE_B 10240
#define SM_AH 0
#define SM_AL 10240
#define SM_BH 20480
#define SM_BL 30720
#define GSM_B 40960

__global__ __launch_bounds__(256, 1)
void k_gemm_mma(const float* __restrict__ bias) {
    extern __shared__ __align__(16) char sm[];
    int tid = threadIdx.x, wid = tid >> 5, lane = tid & 31;
    int bx = blockIdx.x, by = blockIdx.y;  // bx over N/128, by over M/128
    int warp_m = (wid >> 2) * 64;
    int warp_n = (wid & 3) * 32;

    uint32_t smb = smem_u32(sm);

    // per-thread global->smem mapping: 8 vectors of 16B (2 per term tile)
    // vector v in [0,512): row = v>>2, c8 = v&3  (8 bf16 each)
    const __nv_bfloat16* srcs[4];
    srcs[0] = gAh + (size_t)(by * 128) * Dd;
    srcs[1] = gAl + (size_t)(by * 128) * Dd;
    srcs[2] = gBh + (size_t)(bx * 128) * Dd;
    srcs[3] = gBl + (size_t)(bx * 128) * Dd;

    int v0 = tid, v1 = tid + 256;
    int r0 = v0 >> 2, c80 = v0 & 3;
    int r1 = v1 >> 2, c81 = v1 & 3;
    uint32_t sta[8];
#pragma unroll
    for (int t = 0; t < 4; t++) {
        sta[t * 2 + 0] = smb + t * TILE_B + (uint32_t)(r0 * STR + c80 * 8) * 2;
        sta[t * 2 + 1] = smb + t * TILE_B + (uint32_t)(r1 * STR + c81 * 8) * 2;
    }

    // ldmatrix source addresses (per kstep add ks*2 bytes)
    int aRow = warp_m + ((lane >> 3) & 1) * 8 + (lane & 7);
    int aCol = (lane >> 4) << 3;
    int bRow = warp_n + ((lane >> 4) << 3) + (lane & 7);
    int bCol = ((lane >> 3) & 1) << 3;
    uint32_t aAd[4], bAd[2];
#pragma unroll
    for (int mt = 0; mt < 4; mt++)
        aAd[mt] = smb + (uint32_t)((aRow + mt * 16) * STR + aCol) * 2;
#pragma unroll
    for (int p = 0; p < 2; p++)
        bAd[p] = smb + (uint32_t)((bRow + p * 16) * STR + bCol) * 2;

    float acc[4][4][4];
#pragma unroll
    for (int mt = 0; mt < 4; mt++)
#pragma unroll
        for (int nt = 0; nt < 4; nt++)
#pragma unroll
            for (int q = 0; q < 4; q++) acc[mt][nt][q] = 0.f;

    int4 pf[8];
#pragma unroll
    for (int t = 0; t < 4; t++) {
        pf[t * 2 + 0] = *(const int4*)(srcs[t] + (size_t)r0 * Dd + c80 * 8);
        pf[t * 2 + 1] = *(const int4*)(srcs[t] + (size_t)r1 * Dd + c81 * 8);
    }

    const int NCH = Dd / KC;  // 128
    for (int c = 0; c < NCH; c++) {
#pragma unroll
        for (int q = 0; q < 8; q++)
            *(int4*)(sm + (sta[q] - smb)) = pf[q];
        __syncthreads();

        if (c + 1 < NCH) {
            int koff = (c + 1) * KC;
#pragma unroll
            for (int t = 0; t < 4; t++) {
                pf[t * 2 + 0] = *(const int4*)(srcs[t] + (size_t)r0 * Dd + koff + c80 * 8);
                pf[t * 2 + 1] = *(const int4*)(srcs[t] + (size_t)r1 * Dd + koff + c81 * 8);
            }
        }

#pragma unroll
        for (int ks = 0; ks < 2; ks++) {
            uint32_t kb = (uint32_t)(ks * 16 * 2);
            uint32_t aH[4][4], bH[2][4], aL[4][4], bL[2][4];
#pragma unroll
            for (int mt = 0; mt < 4; mt++) ldsm4(aH[mt], aAd[mt] + SM_AH + kb);
#pragma unroll
            for (int p = 0; p < 2; p++) ldsm4(bH[p], bAd[p] + SM_BH + kb);
            // hh
#pragma unroll
            for (int mt = 0; mt < 4; mt++)
#pragma unroll
                for (int nt = 0; nt < 4; nt++)
                    mma16816(acc[mt][nt], aH[mt], &bH[nt >> 1][(nt & 1) << 1]);
#pragma unroll
            for (int mt = 0; mt < 4; mt++) ldsm4(aL[mt], aAd[mt] + SM_AL + kb);
            // lh
#pragma unroll
            for (int mt = 0; mt < 4; mt++)
#pragma unroll
                for (int nt = 0; nt < 4; nt++)
                    mma16816(acc[mt][nt], aL[mt], &bH[nt >> 1][(nt & 1) << 1]);
#pragma unroll
            for (int p = 0; p < 2; p++) ldsm4(bL[p], bAd[p] + SM_BL + kb);
            // hl
#pragma unroll
            for (int mt = 0; mt < 4; mt++)
#pragma unroll
                for (int nt = 0; nt < 4; nt++)
                    mma16816(acc[mt][nt], aH[mt], &bL[nt >> 1][(nt & 1) << 1]);
        }
        __syncthreads();
    }

    // epilogue: acc frag (mt,nt): rows lane/4 and lane/4+8, cols 2*(lane%4)+{0,1}
    int erow = by * 128 + warp_m + (lane >> 2);
    int ecol = bx * 128 + warp_n + (lane & 3) * 2;
#pragma unroll
    for (int mt = 0; mt < 4; mt++) {
#pragma unroll
        for (int nt = 0; nt < 4; nt++) {
            int row = erow + mt * 16;
            int col = ecol + nt * 8;
            float b0 = bias[col], b1 = bias[col + 1];
            float2 o0, o1;
            o0.x = fmaxf(acc[mt][nt][0] + b0, 0.f);
            o0.y = fmaxf(acc[mt][nt][1] + b1, 0.f);
            o1.x = fmaxf(acc[mt][nt][2] + b0, 0.f);
            o1.y = fmaxf(acc[mt][nt][3] + b1, 0.f);
            *(float2*)(g_X + (size_t)row * Dd + col) = o0;
            *(float2*)(g_X + (size_t)(row + 8) * Dd + col) = o1;
        }
    }
}

// ---------------- heads: 16 rows / block, smem-tiled ------------------------
__global__ __launch_bounds__(256)
void k_heads2(const float* __restrict__ Wc, const float* __restrict__ bc,
              const float* __restrict__ Wb, const float* __restrict__ bb_,
              float* __restrict__ out) {
    __shared__ float Xs[16][64];
    __shared__ float Ws[64][106];
    __shared__ float ob[16][105];
    int r0 = blockIdx.x * 16, tid = threadIdx.x;
    float acc[7];
#pragma unroll
    for (int it = 0; it < 7; it++) acc[it] = 0.f;

    for (int kc = 0; kc < 64; kc++) {
        for (int q = tid; q < 16 * 64; q += 256) {
            int r = q >> 6, k = q & 63;
            Xs[r][k] = g_X[(size_t)(r0 + r) * Dd + kc * 64 + k];
        }
        for (int q = tid; q < 64 * 105; q += 256) {
            int k = q / 105, cc = q % 105;
            Ws[k][cc] = (cc < NC) ? Wc[(size_t)(kc * 64 + k) * NC + cc]
                                  : Wb[(size_t)(kc * 64 + k) * NBB + (cc - NC)];
        }
        __syncthreads();
#pragma unroll
        for (int it = 0; it < 7; it++) {
            int o = tid + it * 256;
            if (o < 16 * 105) {
                int r = o / 105, cc = o % 105;
                float a = acc[it];
#pragma unroll 8
                for (int k = 0; k < 64; k++) a += Xs[r][k] * Ws[k][cc];
                acc[it] = a;
            }
        }
        __syncthreads();
    }

#pragma unroll
    for (int it = 0; it < 7; it++) {
        int o = tid + it * 256;
        if (o < 16 * 105) {
            int r = o / 105, cc = o % 105;
            ob[r][cc] = acc[it] + ((cc < NC) ? bc[cc] : bb_[cc - NC]);
        }
    }
    __syncthreads();

    int w = tid >> 5, lane = tid & 31;
    for (int rr = w; rr < 16; rr += 8) {
        float v = (lane < NC) ? ob[rr][lane] : -3.4e38f;
        float m = v;
        for (int o = 16; o; o >>= 1) m = fmaxf(m, __shfl_xor_sync(0xffffffffu, m, o));
        float e = (lane < NC) ? expf(v - m) : 0.f;
        float s = e;
        for (int o = 16; o; o >>= 1) s += __shfl_xor_sync(0xffffffffu, s, o);
        if (lane < NC) out[(size_t)(r0 + rr) * NOUT + lane] = e / s;
    }
    for (int q = tid; q < 16 * NBB; q += 256) {
        int rr = q / NBB, cc = NC + q % NBB;
        out[(size_t)(r0 + rr) * NOUT + cc] = ob[rr][cc];
    }
}

// ---------------- host orchestration ----------------------------------------
extern "C" void kernel_launch(void* const* d_in, const int* in_sizes, int n_in,
                              void* d_out, int out_size) {
    const float* rois = (const float*)d_in[0];
    const float* P    = (const float*)d_in[1];
    const float* W1   = (const float*)d_in[2];
    const float* b1   = (const float*)d_in[3];
    const float* W2   = (const float*)d_in[4];
    const float* b2   = (const float*)d_in[5];
    const float* Wc   = (const float*)d_in[6];
    const float* bc   = (const float*)d_in[7];
    const float* Wb   = (const float*)d_in[8];
    const float* bb   = (const float*)d_in[9];
    float* out = (float*)d_out;

    void* xaddr = nullptr;
    cudaGetSymbolAddress(&xaddr, g_X);

    k_keys<<<1, 1>>>();
    k_boxprep<<<(Nn + 255) / 256, 256>>>(rois);
    k_lens<<<Nn, 256>>>(P);
    k_mask<<<Nn, 256>>>();
    k_sim<<<Nn, 256>>>(P);

    dim3 ggrid(Dd / 128, Nn / 128);  // (32, 16)

    // layer 1
    k_sparse<<<Nn, 256>>>(P);                             // g_Z = adj @ P
    k_cvtA<<<(Nn * Dd) / (4 * 256), 256>>>();
    k_cvtW<<<dim3(Dd / 32, Dd / 32), 256>>>(W1);
    k_gemm_mma<<<ggrid, 256, GSM_B>>>(b1);                // g_X = relu(.@W1+b1)

    // layer 2
    k_sparse<<<Nn, 256>>>((const float*)xaddr);           // g_Z = adj @ g_X
    k_cvtA<<<(Nn * Dd) / (4 * 256), 256>>>();
    k_cvtW<<<dim3(Dd / 32, Dd / 32), 256>>>(W2);
    k_gemm_mma<<<ggrid, 256, GSM_B>>>(b2);                // g_X = relu(.@W2+b2)

    k_heads2<<<Nn / 16, 256>>>(Wc, bc, Wb, bb, out);
}